// round 8
// baseline (speedup 1.0000x reference)
#include <cuda_runtime.h>

#define TB      64      // batch rows per CTA
#define RPAD    66      // row stride (floats), even => aligned float2 row-pairs
#define NTHREADS 512
#define OMEGA_F 30.0f

// ---------- f32x2 packed math (Blackwell FFMA2) ----------
static __device__ __forceinline__ unsigned long long pack2(float a, float b) {
    unsigned long long r;
    asm("mov.b64 %0, {%1, %2};" : "=l"(r) : "f"(a), "f"(b));
    return r;
}
static __device__ __forceinline__ void unpack2(unsigned long long v, float &a, float &b) {
    asm("mov.b64 {%0, %1}, %2;" : "=f"(a), "=f"(b) : "l"(v));
}
static __device__ __forceinline__ unsigned long long fma2(unsigned long long a,
                                                          unsigned long long b,
                                                          unsigned long long c) {
    unsigned long long d;
    asm("fma.rn.f32x2 %0, %1, %2, %3;" : "=l"(d) : "l"(a), "l"(b), "l"(c));
    return d;
}

// ---------------------------------------------------------------------------
// Reformatted weight store: per layer, [K/2][N] ulonglong2,
//   elem(k2,n) = { pack2(W[n][2k2],W[n][2k2]), pack2(W[n][2k2+1],W[n][2k2+1]) }
// ---------------------------------------------------------------------------
#define OFF_ENC1 0
#define OFF_ENC2 4096
#define OFF_RES1 20480
#define OFF_RES2 36864
#define OFF_RES3 45056
#define OFF_POL1 61440
#define OFF_POL2 61696
#define OFF_EXP1 69888
#define OFF_EXP2 299264
#define WT_TOTAL 528640

__device__ ulonglong2 g_wt[WT_TOTAL];

__global__ void reformat_w(const float* __restrict__ src, int dst_off,
                           int N, int K, int NB)
{
    int idx = blockIdx.x * blockDim.x + threadIdx.x;
    int K2 = K / 2;
    int total = NB * K2 * N;
    if (idx >= total) return;
    int n  = idx % N;
    int t  = idx / N;
    int k2 = t % K2;
    int nb = t / K2;
    const float* s = src + ((long long)(nb * N + n)) * K + 2 * k2;
    float w0 = s[0], w1 = s[1];
    ulonglong2 v;
    v.x = pack2(w0, w0);
    v.y = pack2(w1, w1);
    g_wt[dst_off + idx] = v;
}

// Shared memory layout (floats)
#define SM_BUFE 0
#define SM_BUFT (256 * RPAD)
#define SM_BUFU (2 * 256 * RPAD)
#define SM_WBUF (3 * 256 * RPAD)            // 16 KB weight stage (ulonglong2)
#define SM_XS   (SM_WBUF + 4096)
#define SM_PROB (SM_XS + 4 * RPAD)
#define SM_YACC (SM_PROB + 7 * TB)
#define SM_SCR  (SM_YACC + TB)
#define SM_TOTAL (SM_SCR + 8 * TB)

// ---------------------------------------------------------------------------
// Fused GEMM layer, smem-staged pre-duplicated weights.
//   in  : smem activations, [K][RPAD] feature-major
//   Wt  : g_wt region, [K/2][N] ulonglong2
//   out : smem activations, [N][RPAD]
//   ACT : 0 = sin(OMEGA*z), 1 = relu(z), 2 = relu(z + res)
// 512 threads, 16 warps; warp owns 4 rows (2 row-pairs); cols n = lane + 32j.
// Chunk = 16 KB of dup'd weights (CK = 1024/N k-pairs), register-prefetched.
// Per k-pair per thread: 4 LDS.64 (a) + NCOL LDS.128 (w) + 4*NCOL FFMA2.
// ---------------------------------------------------------------------------
template <int K, int NCOL, int ACT>
static __device__ __forceinline__ void gemm_s(
    const float* __restrict__ in, const ulonglong2* __restrict__ Wt,
    const float* __restrict__ bias, float* __restrict__ out,
    ulonglong2* __restrict__ wbuf, const float* __restrict__ res)
{
    constexpr int N   = NCOL * 32;
    constexpr int K2  = K / 2;
    constexpr int CK  = 1024 / N;            // k-pairs per 16KB chunk (4 or 8)
    static_assert(K2 % CK == 0, "K2 % CK");

    const int tid  = threadIdx.x;
    const int lane = tid & 31;
    const int warp = tid >> 5;
    const int r0   = warp * 4;

    unsigned long long acc[2][NCOL];
#pragma unroll
    for (int i = 0; i < 2; i++)
#pragma unroll
        for (int j = 0; j < NCOL; j++) acc[i][j] = 0ull;

    // prefetch chunk 0 (2 ulonglong2 per thread)
    ulonglong2 wr[2];
#pragma unroll
    for (int l = 0; l < 2; l++)
        wr[l] = __ldg(Wt + tid + NTHREADS * l);

    for (int c = 0; c < K2 / CK; c++) {
        // commit prefetched chunk
#pragma unroll
        for (int l = 0; l < 2; l++)
            wbuf[tid + NTHREADS * l] = wr[l];
        __syncthreads();

        // prefetch next chunk
        if ((c + 1) * CK < K2) {
            const ulonglong2* src = Wt + (c + 1) * (CK * N);
#pragma unroll
            for (int l = 0; l < 2; l++)
                wr[l] = __ldg(src + tid + NTHREADS * l);
        }

#pragma unroll
        for (int kc = 0; kc < CK; kc++) {
            const int k = 2 * (c * CK + kc);
            const float* a0p = in + k * RPAD + r0;
            const float* a1p = a0p + RPAD;
            unsigned long long a0[2], a1[2];
#pragma unroll
            for (int i = 0; i < 2; i++) {        // broadcast LDS.64 row-pairs
                a0[i] = *(const unsigned long long*)(a0p + 2 * i);
                a1[i] = *(const unsigned long long*)(a1p + 2 * i);
            }
            const ulonglong2* wrow = wbuf + kc * N + lane;
#pragma unroll
            for (int j = 0; j < NCOL; j++) {
                ulonglong2 w = wrow[32 * j];     // LDS.128, conflict-free
#pragma unroll
                for (int i = 0; i < 2; i++) acc[i][j] = fma2(a0[i], w.x, acc[i][j]);
#pragma unroll
                for (int i = 0; i < 2; i++) acc[i][j] = fma2(a1[i], w.y, acc[i][j]);
            }
        }
        __syncthreads();
    }

    // epilogue: bias + activation, store transposed [n][row] as float2
#pragma unroll
    for (int j = 0; j < NCOL; j++) {
        int n = lane + 32 * j;
        float b = __ldg(bias + n);
#pragma unroll
        for (int i = 0; i < 2; i++) {
            float z0, z1;
            unpack2(acc[i][j], z0, z1);
            z0 += b; z1 += b;
            if (ACT == 0) {
                z0 = __sinf(OMEGA_F * z0);
                z1 = __sinf(OMEGA_F * z1);
            } else if (ACT == 1) {
                z0 = fmaxf(z0, 0.0f);
                z1 = fmaxf(z1, 0.0f);
            } else {
                float2 rv = *(const float2*)(res + n * RPAD + r0 + 2 * i);
                z0 = fmaxf(z0 + rv.x, 0.0f);
                z1 = fmaxf(z1 + rv.y, 0.0f);
            }
            *(float2*)(out + n * RPAD + r0 + 2 * i) = make_float2(z0, z1);
        }
    }
    __syncthreads();
}

// Small-K variant: whole weight staged at once (K2*N <= 1024). For pol_s1 (K=4).
template <int K, int NCOL, int ACT>
static __device__ __forceinline__ void gemm_small(
    const float* __restrict__ in, const ulonglong2* __restrict__ Wt,
    const float* __restrict__ bias, float* __restrict__ out,
    ulonglong2* __restrict__ wbuf)
{
    constexpr int N  = NCOL * 32;
    constexpr int K2 = K / 2;
    const int tid  = threadIdx.x;
    const int lane = tid & 31;
    const int warp = tid >> 5;
    const int r0   = warp * 4;

    for (int idx = tid; idx < K2 * N; idx += NTHREADS)
        wbuf[idx] = __ldg(Wt + idx);
    __syncthreads();

    unsigned long long acc[2][NCOL];
#pragma unroll
    for (int i = 0; i < 2; i++)
#pragma unroll
        for (int j = 0; j < NCOL; j++) acc[i][j] = 0ull;

#pragma unroll
    for (int k2 = 0; k2 < K2; k2++) {
        const int k = 2 * k2;
        const float* a0p = in + k * RPAD + r0;
        const float* a1p = a0p + RPAD;
        unsigned long long a0[2], a1[2];
#pragma unroll
        for (int i = 0; i < 2; i++) {
            a0[i] = *(const unsigned long long*)(a0p + 2 * i);
            a1[i] = *(const unsigned long long*)(a1p + 2 * i);
        }
        const ulonglong2* wrow = wbuf + k2 * N + lane;
#pragma unroll
        for (int j = 0; j < NCOL; j++) {
            ulonglong2 w = wrow[32 * j];
#pragma unroll
            for (int i = 0; i < 2; i++) acc[i][j] = fma2(a0[i], w.x, acc[i][j]);
#pragma unroll
            for (int i = 0; i < 2; i++) acc[i][j] = fma2(a1[i], w.y, acc[i][j]);
        }
    }

#pragma unroll
    for (int j = 0; j < NCOL; j++) {
        int n = lane + 32 * j;
        float b = __ldg(bias + n);
#pragma unroll
        for (int i = 0; i < 2; i++) {
            float z0, z1;
            unpack2(acc[i][j], z0, z1);
            z0 += b; z1 += b;
            if (ACT == 0) {
                z0 = __sinf(OMEGA_F * z0);
                z1 = __sinf(OMEGA_F * z1);
            } else {
                z0 = fmaxf(z0, 0.0f);
                z1 = fmaxf(z1, 0.0f);
            }
            *(float2*)(out + n * RPAD + r0 + 2 * i) = make_float2(z0, z1);
        }
    }
    __syncthreads();
}

// ---------------------------------------------------------------------------
__global__ void __launch_bounds__(NTHREADS, 1)
moe_inr_kernel(
    const float* __restrict__ x,
    const float* __restrict__ enc_s1_b, const float* __restrict__ enc_s2_b,
    const float* __restrict__ res_fc1_b, const float* __restrict__ res_fc2_b,
    const float* __restrict__ res_fc3_b,
    const float* __restrict__ pol_s1_b, const float* __restrict__ pol_s2_b,
    const float* __restrict__ gate_w, const float* __restrict__ gate_b,
    const float* __restrict__ exp_s1_b, const float* __restrict__ exp_s2_b,
    const float* __restrict__ exp_fin_w, const float* __restrict__ exp_fin_b,
    float* __restrict__ out)
{
    extern __shared__ float smem[];
    float* bufE  = smem + SM_BUFE;
    float* bufT  = smem + SM_BUFT;
    float* bufU  = smem + SM_BUFU;
    ulonglong2* wbuf = (ulonglong2*)(smem + SM_WBUF);
    float* xs    = smem + SM_XS;
    float* probs = smem + SM_PROB;
    float* yacc  = smem + SM_YACC;
    float* scr   = smem + SM_SCR;

    const int tid = threadIdx.x;
    const long long rowbase = (long long)blockIdx.x * TB;

    // ---- load x tile: [4][RPAD] feature-major ----
    if (tid < TB * 4) {
        int r = tid >> 2, d = tid & 3;
        xs[d * RPAD + r] = x[(rowbase + r) * 4 + d];
    }
    __syncthreads();

    // ---- positional encoding -> bufT rows [0,64): col = d*16+f; f<8 sin else cos ----
    for (int idx = tid; idx < 64 * TB; idx += NTHREADS) {
        int r = idx & (TB - 1), c = idx / TB;
        int d = c >> 4, f = c & 15;
        float freq = exp2f((float)(f & 7)) * 3.14159265358979323846f;
        float ang  = xs[d * RPAD + r] * freq;
        bufT[c * RPAD + r] = (f < 8) ? sinf(ang) : cosf(ang);
    }
    __syncthreads();

    // ---- encoder ----
    gemm_s< 64, 4, 0>(bufT, g_wt + OFF_ENC1, enc_s1_b,  bufU, wbuf, nullptr);
    gemm_s<128, 8, 0>(bufU, g_wt + OFF_ENC2, enc_s2_b,  bufE, wbuf, nullptr);
    gemm_s<256, 4, 1>(bufE, g_wt + OFF_RES1, res_fc1_b, bufT, wbuf, nullptr);
    gemm_s<128, 4, 1>(bufT, g_wt + OFF_RES2, res_fc2_b, bufU, wbuf, nullptr);
    gemm_s<128, 8, 2>(bufU, g_wt + OFF_RES3, res_fc3_b, bufE, wbuf, bufE);

    // ---- policy ----
    gemm_small<4, 4, 0>(xs, g_wt + OFF_POL1, pol_s1_b, bufT, wbuf);
    gemm_s<128, 4, 0>(bufT, g_wt + OFF_POL2, pol_s2_b, bufU, wbuf, nullptr);

    // ---- gate: logits over concat(enc_feat[256], pf[128]) ----
    float* gbuf = bufT;   // dead; 16896 floats available
    for (int idx = tid; idx < 7 * 384; idx += NTHREADS) gbuf[idx] = gate_w[idx];
    __syncthreads();
    if (tid < 7 * TB) {
        int r = tid & (TB - 1), c = tid / TB;
        const float* gw = gbuf + c * 384;
        float s = __ldg(gate_b + c);
        for (int k = 0; k < 256; k++) s += bufE[k * RPAD + r] * gw[k];
        for (int k = 0; k < 128; k++) s += bufU[k * RPAD + r] * gw[256 + k];
        probs[c * TB + r] = s;
    }
    __syncthreads();
    if (tid < TB) {
        int r = tid;
        float m = -1e30f;
        for (int c = 0; c < 7; c++) m = fmaxf(m, probs[c * TB + r]);
        float s = 0.0f, e[7];
        for (int c = 0; c < 7; c++) { e[c] = __expf(probs[c * TB + r] - m); s += e[c]; }
        float inv = 1.0f / s;
        for (int c = 0; c < 7; c++) probs[c * TB + r] = e[c] * inv;
        yacc[r] = 0.0f;
    }
    __syncthreads();

    // ---- experts ----
    for (int e = 0; e < 7; e++) {
        gemm_s<256, 8, 0>(bufE, g_wt + OFF_EXP1 + e * 32768,
                          exp_s1_b + e * 256, bufT, wbuf, nullptr);
        gemm_s<256, 8, 0>(bufT, g_wt + OFF_EXP2 + e * 32768,
                          exp_s2_b + e * 256, bufU, wbuf, nullptr);
        // final linear [256]->1, 8-way split reduction per row
        {
            int part = tid >> 6, r = tid & 63;
            const float* Wf = exp_fin_w + e * 256;
            float s = 0.0f;
            int k0 = part * 32;
            for (int k = k0; k < k0 + 32; k++) s += bufU[k * RPAD + r] * __ldg(Wf + k);
            scr[part * TB + r] = s;
        }
        __syncthreads();
        if (tid < TB) {
            int r = tid;
            float pred = __ldg(exp_fin_b + e);
#pragma unroll
            for (int p = 0; p < 8; p++) pred += scr[p * TB + r];
            yacc[r] += probs[e * TB + r] * pred;
        }
        __syncthreads();
    }

    if (tid < TB) out[rowbase + tid] = yacc[tid];
}

// ---------------------------------------------------------------------------
static inline void launch_reformat(const float* src, int dst_off, int N, int K, int NB)
{
    int total = NB * (K / 2) * N;
    reformat_w<<<(total + 255) / 256, 256>>>(src, dst_off, N, K, NB);
}

extern "C" void kernel_launch(void* const* d_in, const int* in_sizes, int n_in,
                              void* d_out, int out_size)
{
    const float* x         = (const float*)d_in[0];
    const float* enc_s1_w  = (const float*)d_in[1];
    const float* enc_s1_b  = (const float*)d_in[2];
    const float* enc_s2_w  = (const float*)d_in[3];
    const float* enc_s2_b  = (const float*)d_in[4];
    const float* res_fc1_w = (const float*)d_in[5];
    const float* res_fc1_b = (const float*)d_in[6];
    const float* res_fc2_w = (const float*)d_in[7];
    const float* res_fc2_b = (const float*)d_in[8];
    const float* res_fc3_w = (const float*)d_in[9];
    const float* res_fc3_b = (const float*)d_in[10];
    const float* pol_s1_w  = (const float*)d_in[11];
    const float* pol_s1_b  = (const float*)d_in[12];
    const float* pol_s2_w  = (const float*)d_in[13];
    const float* pol_s2_b  = (const float*)d_in[14];
    const float* gate_w    = (const float*)d_in[15];
    const float* gate_b    = (const float*)d_in[16];
    const float* exp_s1_w  = (const float*)d_in[17];
    const float* exp_s1_b  = (const float*)d_in[18];
    const float* exp_s2_w  = (const float*)d_in[19];
    const float* exp_s2_b  = (const float*)d_in[20];
    const float* exp_fin_w = (const float*)d_in[21];
    const float* exp_fin_b = (const float*)d_in[22];

    launch_reformat(enc_s1_w,  OFF_ENC1, 128,  64, 1);
    launch_reformat(enc_s2_w,  OFF_ENC2, 256, 128, 1);
    launch_reformat(res_fc1_w, OFF_RES1, 128, 256, 1);
    launch_reformat(res_fc2_w, OFF_RES2, 128, 128, 1);
    launch_reformat(res_fc3_w, OFF_RES3, 256, 128, 1);
    launch_reformat(pol_s1_w,  OFF_POL1, 128,   4, 1);
    launch_reformat(pol_s2_w,  OFF_POL2, 128, 128, 1);
    launch_reformat(exp_s1_w,  OFF_EXP1, 256, 256, 7);
    launch_reformat(exp_s2_w,  OFF_EXP2, 256, 256, 7);

    int B = in_sizes[0] / 4;
    int grid = B / TB;
    size_t shmem = (size_t)SM_TOTAL * sizeof(float);

    cudaFuncSetAttribute(moe_inr_kernel,
                         cudaFuncAttributeMaxDynamicSharedMemorySize, (int)shmem);

    moe_inr_kernel<<<grid, NTHREADS, shmem>>>(
        x, enc_s1_b, enc_s2_b,
        res_fc1_b, res_fc2_b, res_fc3_b,
        pol_s1_b, pol_s2_b, gate_w, gate_b,
        exp_s1_b, exp_s2_b, exp_fin_w, exp_fin_b,
        (float*)d_out);
}